// round 14
// baseline (speedup 1.0000x reference)
#include <cuda_runtime.h>
#include <cstdint>

#define B_   2048
#define T_   200
#define F_   64
#define H_   128
#define IN_  256
#define BR   14    // batch rows per block
#define NP   7     // row pairs
#define NT   896   // 28 warps: 128 cols x 7 k-groups
#define NB   147
#define UPITCH 20  // floats per staged row

// reduction pitches (u64) — ODD (bank safety)
#define RZP  23    // rzi groups (6 producers): r@0 z@8 i@16 (7 each, padded)
#define HGP  15    // hn@0..6, gamma@7..13

typedef unsigned long long u64;

// ---------- packed weights ----------
__device__ __align__(16) float g_Wrzi[64*384*4];
__device__ __align__(16) float g_Whn [32*128*4];   // [k4h][j][ks] = w_hh[256+j][4k4h+ks]
__device__ __align__(16) float g_Wdh4[16*128*4];   // [f4][j][ks]  = Wdh[j][4f4+ks]

__global__ void prep_kernel(const float* __restrict__ w_ih,
                            const float* __restrict__ w_hh,
                            const float* __restrict__ Wdh) {
    int idx = blockIdx.x * blockDim.x + threadIdx.x;
    int stride = gridDim.x * blockDim.x;
    const int total1 = 64*384*4;
    for (int i = idx; i < total1; i += stride) {
        int ks = i & 3;
        int c  = (i >> 2) % 384;
        int k4 = i / (4*384);
        int k  = 4*k4 + ks;
        float v = w_ih[c*IN_ + k];
        if (c < 256 && k >= 64 && k < 192) v += w_hh[c*H_ + (k - 64)];
        g_Wrzi[i] = v;
    }
    const int total2 = 32*128*4;
    for (int i = idx; i < total2; i += stride) {
        int ks = i & 3;
        int jj = (i >> 2) % 128;
        int k4 = i / (4*128);
        g_Whn[i] = w_hh[(256 + jj)*H_ + 4*k4 + ks];
    }
    const int total3 = 16*128*4;
    for (int i = idx; i < total3; i += stride) {
        int ks = i & 3;
        int jj = (i >> 2) % 128;
        int f4 = i / (4*128);
        g_Wdh4[i] = Wdh[jj*F_ + 4*f4 + ks];
    }
}

// ---------- f32x2 packed helpers ----------
__device__ __forceinline__ u64 pack2(float a, float b) {
    u64 r; asm("mov.b64 %0,{%1,%2};" : "=l"(r) : "f"(a), "f"(b)); return r;
}
__device__ __forceinline__ void unpack2(u64 v, float& a, float& b) {
    asm("mov.b64 {%0,%1},%2;" : "=f"(a), "=f"(b) : "l"(v));
}
__device__ __forceinline__ u64 fma2(u64 a, u64 b, u64 c) {
    u64 d; asm("fma.rn.f32x2 %0,%1,%2,%3;" : "=l"(d) : "l"(a), "l"(b), "l"(c)); return d;
}
__device__ __forceinline__ u64 add2(u64 a, u64 b) {
    u64 d; asm("add.rn.f32x2 %0,%1,%2;" : "=l"(d) : "l"(a), "l"(b)); return d;
}
__device__ __forceinline__ float sigmoidf_(float x) {
    return __fdividef(1.f, 1.f + __expf(-x));
}
__device__ __forceinline__ float tanhf_(float x) {
    return 1.f - __fdividef(2.f, __expf(2.f * x) + 1.f);
}

// r/z/i GEMM over N4 k4s (R12-proven: unroll 2, linear addressing).
template<int N4>
__device__ __forceinline__ void gemm_rzi(const float* u0, const float4* wb, int j,
                                         u64* ar, u64* az, u64* ai) {
    #pragma unroll 2
    for (int k4 = 0; k4 < N4; k4++) {
        float4 w0 = wb[k4*384 + j];
        float4 w1 = wb[k4*384 + j + 128];
        float4 w2 = wb[k4*384 + j + 256];
        #pragma unroll
        for (int ks = 0; ks < 4; ks++) {
            float f0 = (&w0.x)[ks], f1 = (&w1.x)[ks], f2 = (&w2.x)[ks];
            u64 wr = pack2(f0, f0);
            u64 wz = pack2(f1, f1);
            u64 wn = pack2(f2, f2);
            const float* ub = u0 + (4*k4 + ks) * UPITCH;
            ulonglong2 u01 = *reinterpret_cast<const ulonglong2*>(ub);
            ulonglong2 u23 = *reinterpret_cast<const ulonglong2*>(ub + 4);
            ulonglong2 u45 = *reinterpret_cast<const ulonglong2*>(ub + 8);
            u64        u6  = *reinterpret_cast<const u64*>(ub + 12);
            ar[0]=fma2(u01.x,wr,ar[0]); az[0]=fma2(u01.x,wz,az[0]); ai[0]=fma2(u01.x,wn,ai[0]);
            ar[1]=fma2(u01.y,wr,ar[1]); az[1]=fma2(u01.y,wz,az[1]); ai[1]=fma2(u01.y,wn,ai[1]);
            ar[2]=fma2(u23.x,wr,ar[2]); az[2]=fma2(u23.x,wz,az[2]); ai[2]=fma2(u23.x,wn,ai[2]);
            ar[3]=fma2(u23.y,wr,ar[3]); az[3]=fma2(u23.y,wz,az[3]); ai[3]=fma2(u23.y,wn,ai[3]);
            ar[4]=fma2(u45.x,wr,ar[4]); az[4]=fma2(u45.x,wz,az[4]); ai[4]=fma2(u45.x,wn,ai[4]);
            ar[5]=fma2(u45.y,wr,ar[5]); az[5]=fma2(u45.y,wz,az[5]); ai[5]=fma2(u45.y,wn,ai[5]);
            ar[6]=fma2(u6,   wr,ar[6]); az[6]=fma2(u6,   wz,az[6]); ai[6]=fma2(u6,   wn,ai[6]);
        }
    }
}

// single-column GEMM (hn or gamma), weight stride 128 float4/k4.
template<int N4>
__device__ __forceinline__ void gemm_hn(const float* u0, const float4* wb, int j,
                                        u64* ah) {
    #pragma unroll 2
    for (int k4 = 0; k4 < N4; k4++) {
        float4 w = wb[k4*128 + j];
        #pragma unroll
        for (int ks = 0; ks < 4; ks++) {
            float fv = (&w.x)[ks];
            u64 wn = pack2(fv, fv);
            const float* ub = u0 + (4*k4 + ks) * UPITCH;
            ulonglong2 u01 = *reinterpret_cast<const ulonglong2*>(ub);
            ulonglong2 u23 = *reinterpret_cast<const ulonglong2*>(ub + 4);
            ulonglong2 u45 = *reinterpret_cast<const ulonglong2*>(ub + 8);
            u64        u6  = *reinterpret_cast<const u64*>(ub + 12);
            ah[0]=fma2(u01.x,wn,ah[0]); ah[1]=fma2(u01.y,wn,ah[1]);
            ah[2]=fma2(u23.x,wn,ah[2]); ah[3]=fma2(u23.y,wn,ah[3]);
            ah[4]=fma2(u45.x,wn,ah[4]); ah[5]=fma2(u45.y,wn,ah[5]);
            ah[6]=fma2(u6,   wn,ah[6]);
        }
    }
}

// smem: staging 40960 + rzired 6*128*23*8 + hgred 2*128*15*8 + consts
#define RZI_U64 (6*128*RZP)
#define HG_U64  (2*128*HGP)
#define SMEM_BYTES ((128 + 2*128 + 2*64)*UPITCH*4 + (RZI_U64 + HG_U64)*8 + 3*F_*4 + 4*BR*4)

__global__ void __launch_bounds__(NT, 1) grud_kernel(
    const float* __restrict__ values, const float* __restrict__ masks,
    const float* __restrict__ deltas, const float* __restrict__ xlocf,
    const float* __restrict__ emp_mean, const float* __restrict__ bdh,
    const float* __restrict__ Wdx, const float* __restrict__ bdx,
    const float* __restrict__ b_ih, const float* __restrict__ b_hh,
    const float* __restrict__ Wc, const float* __restrict__ bc,
    float* __restrict__ out)
{
    extern __shared__ char smem_raw[];
    float* hsh = reinterpret_cast<float*>(smem_raw);   // [128][UPITCH]: decayed h
    float* xm0 = hsh + 128*UPITCH;                     // [128][UPITCH]: x 0-63, m 64-127
    float* xm1 = xm0 + 128*UPITCH;
    float* ds0 = xm1 + 128*UPITCH;                     // [64][UPITCH] raw deltas
    float* ds1 = ds0 + 64*UPITCH;
    u64*   rzired = reinterpret_cast<u64*>(ds1 + 64*UPITCH);  // [6][128][RZP]
    u64*   hgred  = rzired + RZI_U64;                          // [2][128][HGP]
    float* s_emp  = reinterpret_cast<float*>(hgred + HG_U64);
    float* s_wdx  = s_emp + F_;
    float* s_bdx  = s_wdx + F_;
    float* s_redf = s_bdx + F_;                                // [4][BR]

    const int tid = threadIdx.x;
    const int j   = tid & 127;
    const int kg  = tid >> 7;    // 0..6
    const int r0  = blockIdx.x * BR;

    if (tid < F_) {
        s_emp[tid] = emp_mean[tid];
        s_wdx[tid] = Wdx[tid * F_ + tid];
        s_bdx[tid] = bdx[tid];
    }
    for (int i = tid; i < 128*UPITCH; i += NT) hsh[i] = 0.f;   // h0 = 0

    const float bdh_j = bdh[j];
    const float br_   = b_ih[j]        + b_hh[j];
    const float bz_   = b_ih[H_ + j]   + b_hh[H_ + j];
    const float bin_  = b_ih[2*H_ + j];
    const float bhn_  = b_hh[2*H_ + j];
    const float wc_j  = Wc[j];

    // stage A mapping (tid<448)
    const int sr   = tid >> 5;
    const int lane = tid & 31;
    const int sf   = lane * 2;
    const int ri   = min(r0 + sr, B_ - 1);
    const size_t rowbase = (size_t)ri * T_ * F_;
    const bool aON = (tid < 448);

    u64* myrzi = rzired + (size_t)(kg*128 + j) * RZP;           // valid kg<6
    u64* myhg  = hgred + (size_t)((kg - 5)*128 + j) * HGP;      // valid kg>=5

    const float4* Wrzi4 = reinterpret_cast<const float4*>(g_Wrzi);
    const float4* Whn4  = reinterpret_cast<const float4*>(g_Whn);
    const float4* Wd4   = reinterpret_cast<const float4*>(g_Wdh4);

    __syncthreads();

    // ---- prologue: x_rep(0), m(0) -> xm0 ; d(1) -> ds1 ----
    if (aON) {
        const size_t base = rowbase + sf;
        float2 xv = *reinterpret_cast<const float2*>(values + base);
        float2 xm = *reinterpret_cast<const float2*>(masks  + base);
        float2 xd = *reinterpret_cast<const float2*>(deltas + base);
        float2 xl = *reinterpret_cast<const float2*>(xlocf  + base);
        float2 d1 = *reinterpret_cast<const float2*>(deltas + rowbase + F_ + sf);
        float v_[2] = {xv.x, xv.y}, m_[2] = {xm.x, xm.y};
        float d_[2] = {xd.x, xd.y}, l_[2] = {xl.x, xl.y};
        float dn[2] = {d1.x, d1.y};
        #pragma unroll
        for (int q = 0; q < 2; q++) {
            int f = sf + q;
            float gx   = __expf(-fmaxf(d_[q]*s_wdx[f] + s_bdx[f], 0.f));
            float xh   = gx*l_[q] + (1.f - gx)*s_emp[f];
            float xrep = m_[q]*v_[q] + (1.f - m_[q])*xh;
            xm0[f*UPITCH      + sr] = xrep;
            xm0[(64+f)*UPITCH + sr] = m_[q];
            ds1[f*UPITCH      + sr] = dn[q];
        }
    }
    __syncthreads();

    for (int t = 0; t < T_; t++) {
        const float* xmc = (t & 1) ? xm1 : xm0;        // u(t)
        float*       xmn = (t & 1) ? xm0 : xm1;        // u(t+1) staging
        const float* dsr = ((t + 1) & 1) ? ds1 : ds0;  // d(t+1)
        float*       dsw = (t & 1) ? ds1 : ds0;        // d(t+2) staging
        const bool doA = aON && (t + 1 < T_);

        // ---- phase 1: stage A(t+1), then balanced 7-way GEMM ----
        if (doA) {
            const size_t base = rowbase + (size_t)(t+1)*F_ + sf;
            float2 xv = *reinterpret_cast<const float2*>(values + base);
            float2 xm = *reinterpret_cast<const float2*>(masks  + base);
            float2 xl = *reinterpret_cast<const float2*>(xlocf  + base);
            float2 d2 = make_float2(0.f, 0.f);
            if (t + 2 < T_)
                d2 = *reinterpret_cast<const float2*>(deltas + rowbase + (size_t)(t+2)*F_ + sf);
            float v_[2] = {xv.x, xv.y}, m_[2] = {xm.x, xm.y}, l_[2] = {xl.x, xl.y};
            #pragma unroll
            for (int q = 0; q < 2; q++) {
                int f = sf + q;
                float dv   = dsr[f*UPITCH + sr];
                float gx   = __expf(-fmaxf(dv*s_wdx[f] + s_bdx[f], 0.f));
                float xh   = gx*l_[q] + (1.f - gx)*s_emp[f];
                float xrep = m_[q]*v_[q] + (1.f - m_[q])*xh;
                xmn[f*UPITCH      + sr] = xrep;
                xmn[(64+f)*UPITCH + sr] = m_[q];
                if (t + 2 < T_) dsw[f*UPITCH + sr] = (&d2.x)[q];
            }
        }

        // split (slots, max skew ~2.4%):
        // kg0: x k4[0,12)            kg1: x[12,16) + h[16,24)
        // kg2: h[24,36)              kg3: h[36,48)
        // kg4: m[48,60)              kg5: m[60,64) rzi + hn[0,10) + gamma[0,9)
        // kg6: hn[10,32) + gamma[9,16)
        {
            u64 ar[NP], az[NP], ai[NP];
            #pragma unroll
            for (int p = 0; p < NP; p++) { ar[p]=0ull; az[p]=0ull; ai[p]=0ull; }
            switch (kg) {
                case 0:
                    gemm_rzi<12>(xmc,              Wrzi4 + 0*384,  j, ar, az, ai);
                    break;
                case 1:
                    gemm_rzi<4> (xmc + 48*UPITCH,  Wrzi4 + 12*384, j, ar, az, ai);
                    gemm_rzi<8> (hsh,              Wrzi4 + 16*384, j, ar, az, ai);
                    break;
                case 2:
                    gemm_rzi<12>(hsh + 32*UPITCH,  Wrzi4 + 24*384, j, ar, az, ai);
                    break;
                case 3:
                    gemm_rzi<12>(hsh + 80*UPITCH,  Wrzi4 + 36*384, j, ar, az, ai);
                    break;
                case 4:
                    gemm_rzi<12>(xmc + 64*UPITCH,  Wrzi4 + 48*384, j, ar, az, ai);
                    break;
                case 5: {
                    gemm_rzi<4> (xmc + 112*UPITCH, Wrzi4 + 60*384, j, ar, az, ai);
                    #pragma unroll
                    for (int p = 0; p < NP; p++) {
                        myrzi[p] = ar[p]; myrzi[8+p] = az[p]; myrzi[16+p] = ai[p];
                        ar[p] = 0ull;
                    }
                    gemm_hn<10>(hsh, Whn4, j, ar);              // hn k4h [0,10)
                    #pragma unroll
                    for (int p = 0; p < NP; p++) { myhg[p] = ar[p]; ar[p] = 0ull; }
                    if (t + 1 < T_) {
                        gemm_hn<9>(dsr, Wd4, j, ar);            // gamma k4 [0,9)
                        #pragma unroll
                        for (int p = 0; p < NP; p++) myhg[7 + p] = ar[p];
                    }
                    break;
                }
                default: {  // kg6
                    gemm_hn<22>(hsh + 40*UPITCH, Whn4 + 10*128, j, ar);  // hn [10,32)
                    #pragma unroll
                    for (int p = 0; p < NP; p++) { myhg[p] = ar[p]; ar[p] = 0ull; }
                    if (t + 1 < T_) {
                        gemm_hn<7>(dsr + 36*UPITCH, Wd4 + 9*128, j, ar); // gamma [9,16)
                        #pragma unroll
                        for (int p = 0; p < NP; p++) myhg[7 + p] = ar[p];
                    }
                    break;
                }
            }
            if (kg < 5) {
                #pragma unroll
                for (int p = 0; p < NP; p++) {
                    myrzi[p] = ar[p]; myrzi[8+p] = az[p]; myrzi[16+p] = ai[p];
                }
            }
        }
        __syncthreads();   // S1

        // ---- phase 2: reduce + epilogue + gamma apply (one output per thread) ----
        {
            const int p = kg;   // pair index == k-group: 896 outputs exactly
            u64 rv = 0ull, zv = 0ull, iv = 0ull;
            #pragma unroll
            for (int g = 0; g < 6; g++) {
                const u64* s = rzired + (size_t)(g*128 + j) * RZP;
                rv = add2(rv, s[p]);
                zv = add2(zv, s[8+p]);
                iv = add2(iv, s[16+p]);
            }
            const u64* h0 = hgred + (size_t)j * HGP;
            const u64* h1 = hgred + (size_t)(128 + j) * HGP;
            u64 hv = add2(h0[p], h1[p]);
            u64 gv = add2(h0[7+p], h1[7+p]);

            float* hrow = hsh + j*UPITCH;
            float r0f,r1f,z0f,z1f,i0f,i1f,n0f,n1f,h0f,h1f;
            unpack2(rv, r0f, r1f);
            unpack2(zv, z0f, z1f);
            unpack2(iv, i0f, i1f);
            unpack2(hv, n0f, n1f);
            unpack2(*reinterpret_cast<u64*>(hrow + 2*p), h0f, h1f);
            float rr0 = sigmoidf_(r0f + br_);
            float rr1 = sigmoidf_(r1f + br_);
            float zz0 = sigmoidf_(z0f + bz_);
            float zz1 = sigmoidf_(z1f + bz_);
            float nn0 = tanhf_(i0f + bin_ + rr0 * (n0f + bhn_));
            float nn1 = tanhf_(i1f + bin_ + rr1 * (n1f + bhn_));
            float hn0 = (1.f - zz0)*nn0 + zz0*h0f;
            float hn1 = (1.f - zz1)*nn1 + zz1*h1f;
            if (t + 1 < T_) {
                float gp0, gp1;
                unpack2(gv, gp0, gp1);
                float gg0 = __expf(-fmaxf(gp0 + bdh_j, 0.f));
                float gg1 = __expf(-fmaxf(gp1 + bdh_j, 0.f));
                hn0 *= gg0; hn1 *= gg1;
            }
            *reinterpret_cast<u64*>(hrow + 2*p) = pack2(hn0, hn1);
        }
        __syncthreads();   // S2
    }

    // ---- final: logits = h @ Wc.T + bc ; sigmoid ----
    if (tid < 128) {
        float part[BR];
        #pragma unroll
        for (int r = 0; r < BR; r++)
            part[r] = hsh[j*UPITCH + r] * wc_j;
        #pragma unroll
        for (int off = 16; off > 0; off >>= 1) {
            #pragma unroll
            for (int r = 0; r < BR; r++)
                part[r] += __shfl_down_sync(0xffffffffu, part[r], off);
        }
        if ((tid & 31) == 0) {
            int w = tid >> 5;
            #pragma unroll
            for (int r = 0; r < BR; r++) s_redf[w*BR + r] = part[r];
        }
    }
    __syncthreads();
    if (tid < BR && (r0 + tid) < B_) {
        float s = s_redf[0*BR + tid] + s_redf[1*BR + tid]
                + s_redf[2*BR + tid] + s_redf[3*BR + tid] + bc[0];
        out[r0 + tid] = sigmoidf_(s);
    }
}

extern "C" void kernel_launch(void* const* d_in, const int* in_sizes, int n_in,
                              void* d_out, int out_size) {
    const float* values   = (const float*)d_in[0];
    const float* masks    = (const float*)d_in[1];
    const float* deltas   = (const float*)d_in[2];
    const float* x_locf   = (const float*)d_in[3];
    const float* emp_mean = (const float*)d_in[4];
    const float* Wdh      = (const float*)d_in[5];
    const float* bdh      = (const float*)d_in[6];
    const float* Wdx      = (const float*)d_in[7];
    const float* bdx      = (const float*)d_in[8];
    const float* w_ih     = (const float*)d_in[9];
    const float* w_hh     = (const float*)d_in[10];
    const float* b_ih     = (const float*)d_in[11];
    const float* b_hh     = (const float*)d_in[12];
    const float* Wc       = (const float*)d_in[13];
    const float* bc       = (const float*)d_in[14];
    float* out = (float*)d_out;

    cudaFuncSetAttribute(grud_kernel,
                         cudaFuncAttributeMaxDynamicSharedMemorySize, SMEM_BYTES);

    prep_kernel<<<576, 256>>>(w_ih, w_hh, Wdh);
    grud_kernel<<<NB, NT, SMEM_BYTES>>>(values, masks, deltas, x_locf, emp_mean,
                                        bdh, Wdx, bdx, b_ih, b_hh, Wc, bc, out);
}

// round 15
// speedup vs baseline: 1.2973x; 1.2973x over previous
#include <cuda_runtime.h>
#include <cstdint>

#define B_   2048
#define T_   200
#define F_   64
#define H_   128
#define IN_  256
#define BR   14    // batch rows per block
#define NP   7     // row pairs
#define NT   768   // 24 warps: 128 cols x 6 k-groups
#define NB   147
#define UPITCH 20  // floats per staged row

// reduction pitches (u64) — ODD to avoid bank-conflict pathology
#define R03P 25    // groups 0..3: r@0 z@8 i@16
#define R4P  33    // group 4:     r@0 z@8 i@16 hn@24
#define R5P  17    // group 5:     hn@0 gamma@8
#define RED_U64 (4*128*R03P + 128*R4P + 128*R5P)

typedef unsigned long long u64;

// ---------- packed weights ----------
__device__ __align__(16) float g_Wrzi[64*384*4];
__device__ __align__(16) float g_Whn [32*128*4];   // [k4h][j][ks] = w_hh[256+j][4k4h+ks]
__device__ __align__(16) float g_Wdh4[16*128*4];   // [f4][j][ks]  = Wdh[j][4f4+ks]

__global__ void prep_kernel(const float* __restrict__ w_ih,
                            const float* __restrict__ w_hh,
                            const float* __restrict__ Wdh) {
    int idx = blockIdx.x * blockDim.x + threadIdx.x;
    int stride = gridDim.x * blockDim.x;
    const int total1 = 64*384*4;
    for (int i = idx; i < total1; i += stride) {
        int ks = i & 3;
        int c  = (i >> 2) % 384;
        int k4 = i / (4*384);
        int k  = 4*k4 + ks;
        float v = w_ih[c*IN_ + k];
        if (c < 256 && k >= 64 && k < 192) v += w_hh[c*H_ + (k - 64)];
        g_Wrzi[i] = v;
    }
    const int total2 = 32*128*4;
    for (int i = idx; i < total2; i += stride) {
        int ks = i & 3;
        int jj = (i >> 2) % 128;
        int k4 = i / (4*128);
        g_Whn[i] = w_hh[(256 + jj)*H_ + 4*k4 + ks];
    }
    const int total3 = 16*128*4;
    for (int i = idx; i < total3; i += stride) {
        int ks = i & 3;
        int jj = (i >> 2) % 128;
        int f4 = i / (4*128);
        g_Wdh4[i] = Wdh[jj*F_ + 4*f4 + ks];
    }
}

// ---------- f32x2 packed helpers ----------
__device__ __forceinline__ u64 pack2(float a, float b) {
    u64 r; asm("mov.b64 %0,{%1,%2};" : "=l"(r) : "f"(a), "f"(b)); return r;
}
__device__ __forceinline__ void unpack2(u64 v, float& a, float& b) {
    asm("mov.b64 {%0,%1},%2;" : "=f"(a), "=f"(b) : "l"(v));
}
__device__ __forceinline__ u64 fma2(u64 a, u64 b, u64 c) {
    u64 d; asm("fma.rn.f32x2 %0,%1,%2,%3;" : "=l"(d) : "l"(a), "l"(b), "l"(c)); return d;
}
__device__ __forceinline__ u64 add2(u64 a, u64 b) {
    u64 d; asm("add.rn.f32x2 %0,%1,%2;" : "=l"(d) : "l"(a), "l"(b)); return d;
}
__device__ __forceinline__ float sigmoidf_(float x) {       // exact path
    return __fdividef(1.f, 1.f + __expf(-x));
}
// fast path: 1 MUFU each (tanh.approx.f32)
__device__ __forceinline__ float tanh_fast(float x) {
    float t; asm("tanh.approx.f32 %0, %1;" : "=f"(t) : "f"(x)); return t;
}
__device__ __forceinline__ float sigmoid_fast(float x) {
    float t; asm("tanh.approx.f32 %0, %1;" : "=f"(t) : "f"(x * 0.5f));
    return fmaf(t, 0.5f, 0.5f);
}

// r/z/i GEMM over N4 k4s (R12-proven: unroll 2, linear addressing).
template<int N4>
__device__ __forceinline__ void gemm_rzi(const float* u0, const float4* wb, int j,
                                         u64* ar, u64* az, u64* ai) {
    #pragma unroll 2
    for (int k4 = 0; k4 < N4; k4++) {
        float4 w0 = wb[k4*384 + j];
        float4 w1 = wb[k4*384 + j + 128];
        float4 w2 = wb[k4*384 + j + 256];
        #pragma unroll
        for (int ks = 0; ks < 4; ks++) {
            float f0 = (&w0.x)[ks], f1 = (&w1.x)[ks], f2 = (&w2.x)[ks];
            u64 wr = pack2(f0, f0);
            u64 wz = pack2(f1, f1);
            u64 wn = pack2(f2, f2);
            const float* ub = u0 + (4*k4 + ks) * UPITCH;
            ulonglong2 u01 = *reinterpret_cast<const ulonglong2*>(ub);
            ulonglong2 u23 = *reinterpret_cast<const ulonglong2*>(ub + 4);
            ulonglong2 u45 = *reinterpret_cast<const ulonglong2*>(ub + 8);
            u64        u6  = *reinterpret_cast<const u64*>(ub + 12);
            ar[0]=fma2(u01.x,wr,ar[0]); az[0]=fma2(u01.x,wz,az[0]); ai[0]=fma2(u01.x,wn,ai[0]);
            ar[1]=fma2(u01.y,wr,ar[1]); az[1]=fma2(u01.y,wz,az[1]); ai[1]=fma2(u01.y,wn,ai[1]);
            ar[2]=fma2(u23.x,wr,ar[2]); az[2]=fma2(u23.x,wz,az[2]); ai[2]=fma2(u23.x,wn,ai[2]);
            ar[3]=fma2(u23.y,wr,ar[3]); az[3]=fma2(u23.y,wz,az[3]); ai[3]=fma2(u23.y,wn,ai[3]);
            ar[4]=fma2(u45.x,wr,ar[4]); az[4]=fma2(u45.x,wz,az[4]); ai[4]=fma2(u45.x,wn,ai[4]);
            ar[5]=fma2(u45.y,wr,ar[5]); az[5]=fma2(u45.y,wz,az[5]); ai[5]=fma2(u45.y,wn,ai[5]);
            ar[6]=fma2(u6,   wr,ar[6]); az[6]=fma2(u6,   wz,az[6]); ai[6]=fma2(u6,   wn,ai[6]);
        }
    }
}

// single-column GEMM (hn or gamma), weight stride 128 float4/k4.
template<int N4>
__device__ __forceinline__ void gemm_hn(const float* u0, const float4* wb, int j,
                                        u64* ah) {
    #pragma unroll 2
    for (int k4 = 0; k4 < N4; k4++) {
        float4 w = wb[k4*128 + j];
        #pragma unroll
        for (int ks = 0; ks < 4; ks++) {
            float fv = (&w.x)[ks];
            u64 wn = pack2(fv, fv);
            const float* ub = u0 + (4*k4 + ks) * UPITCH;
            ulonglong2 u01 = *reinterpret_cast<const ulonglong2*>(ub);
            ulonglong2 u23 = *reinterpret_cast<const ulonglong2*>(ub + 4);
            ulonglong2 u45 = *reinterpret_cast<const ulonglong2*>(ub + 8);
            u64        u6  = *reinterpret_cast<const u64*>(ub + 12);
            ah[0]=fma2(u01.x,wn,ah[0]); ah[1]=fma2(u01.y,wn,ah[1]);
            ah[2]=fma2(u23.x,wn,ah[2]); ah[3]=fma2(u23.y,wn,ah[3]);
            ah[4]=fma2(u45.x,wn,ah[4]); ah[5]=fma2(u45.y,wn,ah[5]);
            ah[6]=fma2(u6,   wn,ah[6]);
        }
    }
}

#define SMEM_BYTES ((128 + 2*128 + 2*64)*UPITCH*4 + RED_U64*8 + 3*F_*4 + 4*BR*4)

__global__ void __launch_bounds__(NT, 1) grud_kernel(
    const float* __restrict__ values, const float* __restrict__ masks,
    const float* __restrict__ deltas, const float* __restrict__ xlocf,
    const float* __restrict__ emp_mean, const float* __restrict__ bdh,
    const float* __restrict__ Wdx, const float* __restrict__ bdx,
    const float* __restrict__ b_ih, const float* __restrict__ b_hh,
    const float* __restrict__ Wc, const float* __restrict__ bc,
    float* __restrict__ out)
{
    extern __shared__ char smem_raw[];
    float* hsh = reinterpret_cast<float*>(smem_raw);   // [128][UPITCH]: decayed h
    float* xm0 = hsh + 128*UPITCH;                     // [128][UPITCH]: x 0-63, m 64-127
    float* xm1 = xm0 + 128*UPITCH;
    float* ds0 = xm1 + 128*UPITCH;                     // [64][UPITCH] raw deltas
    float* ds1 = ds0 + 64*UPITCH;
    u64*   red = reinterpret_cast<u64*>(ds1 + 64*UPITCH);
    float* s_emp  = reinterpret_cast<float*>(red + RED_U64);
    float* s_wdx  = s_emp + F_;
    float* s_bdx  = s_wdx + F_;
    float* s_redf = s_bdx + F_;                         // [4][BR]

    const int tid = threadIdx.x;
    const int j   = tid & 127;
    const int kg  = tid >> 7;    // 0..5
    const int r0  = blockIdx.x * BR;

    if (tid < F_) {
        s_emp[tid] = emp_mean[tid];
        s_wdx[tid] = Wdx[tid * F_ + tid];
        s_bdx[tid] = bdx[tid];
    }
    for (int i = tid; i < 128*UPITCH; i += NT) hsh[i] = 0.f;   // h0 = 0

    const float bdh_j = bdh[j];
    const float br_   = b_ih[j]        + b_hh[j];
    const float bz_   = b_ih[H_ + j]   + b_hh[H_ + j];
    const float bin_  = b_ih[2*H_ + j];
    const float bhn_  = b_hh[2*H_ + j];
    const float wc_j  = Wc[j];

    // stage A mapping (tid<448)
    const int sr   = tid >> 5;
    const int lane = tid & 31;
    const int sf   = lane * 2;
    const int ri   = min(r0 + sr, B_ - 1);
    const size_t rowbase = (size_t)ri * T_ * F_;
    const bool aON = (tid < 448);

    u64* myslot;
    if      (kg < 4)  myslot = red + kg*128*R03P + j*R03P;
    else if (kg == 4) myslot = red + 4*128*R03P + j*R4P;
    else              myslot = red + 4*128*R03P + 128*R4P + j*R5P;

    const float4* Wrzi4 = reinterpret_cast<const float4*>(g_Wrzi);
    const float4* Whn4  = reinterpret_cast<const float4*>(g_Whn);
    const float4* Wd4   = reinterpret_cast<const float4*>(g_Wdh4);

    __syncthreads();

    // ---- prologue: x_rep(0), m(0) -> xm0 ; d(1) -> ds1 ----
    if (aON) {
        const size_t base = rowbase + sf;
        float2 xv = *reinterpret_cast<const float2*>(values + base);
        float2 xm = *reinterpret_cast<const float2*>(masks  + base);
        float2 xd = *reinterpret_cast<const float2*>(deltas + base);
        float2 xl = *reinterpret_cast<const float2*>(xlocf  + base);
        float2 d1 = *reinterpret_cast<const float2*>(deltas + rowbase + F_ + sf);
        float v_[2] = {xv.x, xv.y}, m_[2] = {xm.x, xm.y};
        float d_[2] = {xd.x, xd.y}, l_[2] = {xl.x, xl.y};
        float dn[2] = {d1.x, d1.y};
        #pragma unroll
        for (int q = 0; q < 2; q++) {
            int f = sf + q;
            float gx   = __expf(-fmaxf(d_[q]*s_wdx[f] + s_bdx[f], 0.f));
            float xh   = gx*l_[q] + (1.f - gx)*s_emp[f];
            float xrep = m_[q]*v_[q] + (1.f - m_[q])*xh;
            xm0[f*UPITCH      + sr] = xrep;
            xm0[(64+f)*UPITCH + sr] = m_[q];
            ds1[f*UPITCH      + sr] = dn[q];
        }
    }
    __syncthreads();

    for (int t = 0; t < T_; t++) {
        const float* xmc = (t & 1) ? xm1 : xm0;        // u(t)
        float*       xmn = (t & 1) ? xm0 : xm1;        // u(t+1) staging
        const float* dsr = ((t + 1) & 1) ? ds1 : ds0;  // d(t+1)
        float*       dsw = (t & 1) ? ds1 : ds0;        // d(t+2) staging
        const bool doA = aON && (t + 1 < T_);

        // ---- phase 1: stage A(t+1), then balanced GEMM ----
        if (doA) {
            const size_t base = rowbase + (size_t)(t+1)*F_ + sf;
            float2 xv = *reinterpret_cast<const float2*>(values + base);
            float2 xm = *reinterpret_cast<const float2*>(masks  + base);
            float2 xl = *reinterpret_cast<const float2*>(xlocf  + base);
            float2 d2 = make_float2(0.f, 0.f);
            if (t + 2 < T_)
                d2 = *reinterpret_cast<const float2*>(deltas + rowbase + (size_t)(t+2)*F_ + sf);
            float v_[2] = {xv.x, xv.y}, m_[2] = {xm.x, xm.y}, l_[2] = {xl.x, xl.y};
            #pragma unroll
            for (int q = 0; q < 2; q++) {
                int f = sf + q;
                float dv   = dsr[f*UPITCH + sr];   // d(t+1), staged earlier
                float gx   = __expf(-fmaxf(dv*s_wdx[f] + s_bdx[f], 0.f));
                float xh   = gx*l_[q] + (1.f - gx)*s_emp[f];
                float xrep = m_[q]*v_[q] + (1.f - m_[q])*xh;
                xmn[f*UPITCH      + sr] = xrep;
                xmn[(64+f)*UPITCH + sr] = m_[q];
                if (t + 2 < T_) dsw[f*UPITCH + sr] = (&d2.x)[q];
            }
        }

        // balanced split:
        // kg0: x k4[0,14)                      kg1: x k4[14,16) + h k4[16,28)
        // kg2: h k4[28,42)                     kg3: h k4[42,48) + m k4[48,56)
        // kg4: m k4[56,64) + hn k4h[0,15)      kg5: hn k4h[15,32) + gamma d-k4[0,16)
        {
            u64 ar[NP], az[NP], ai[NP];
            #pragma unroll
            for (int p = 0; p < NP; p++) { ar[p]=0ull; az[p]=0ull; ai[p]=0ull; }
            switch (kg) {
                case 0:
                    gemm_rzi<14>(xmc,               Wrzi4 + 0*384,  j, ar, az, ai);
                    break;
                case 1:
                    gemm_rzi<2> (xmc + 56*UPITCH,   Wrzi4 + 14*384, j, ar, az, ai);
                    gemm_rzi<12>(hsh,               Wrzi4 + 16*384, j, ar, az, ai);
                    break;
                case 2:
                    gemm_rzi<14>(hsh + 48*UPITCH,   Wrzi4 + 28*384, j, ar, az, ai);
                    break;
                case 3:
                    gemm_rzi<6> (hsh + 104*UPITCH,  Wrzi4 + 42*384, j, ar, az, ai);
                    gemm_rzi<8> (xmc + 64*UPITCH,   Wrzi4 + 48*384, j, ar, az, ai);
                    break;
                case 4: {
                    gemm_rzi<8> (xmc + 96*UPITCH,   Wrzi4 + 56*384, j, ar, az, ai);
                    #pragma unroll
                    for (int p = 0; p < NP; p++) {
                        myslot[p] = ar[p]; myslot[8+p] = az[p]; myslot[16+p] = ai[p];
                        ar[p] = 0ull;
                    }
                    gemm_hn<15>(hsh, Whn4, j, ar);          // hn k4h [0,15)
                    #pragma unroll
                    for (int p = 0; p < NP; p++) myslot[24 + p] = ar[p];
                    break;
                }
                default: {
                    gemm_hn<17>(hsh + 60*UPITCH, Whn4 + 15*128, j, ar);  // hn k4h [15,32)
                    #pragma unroll
                    for (int p = 0; p < NP; p++) { myslot[p] = ar[p]; ar[p] = 0ull; }
                    if (t + 1 < T_) {
                        gemm_hn<16>(dsr, Wd4, j, ar);       // gamma d-k4 [0,16)
                        #pragma unroll
                        for (int p = 0; p < NP; p++) myslot[8 + p] = ar[p];
                    }
                    break;
                }
            }
            if (kg < 4) {
                #pragma unroll
                for (int p = 0; p < NP; p++) {
                    myslot[p] = ar[p]; myslot[8+p] = az[p]; myslot[16+p] = ai[p];
                }
            }
        }
        __syncthreads();   // S1

        // ---- phase 2: reduce + epilogue (fast transcendentals) ----
        {
            const u64* s4 = red + 4*128*R03P + j*R4P;
            const u64* s5 = red + 4*128*R03P + 128*R4P + j*R5P;
            float* hrow = hsh + j*UPITCH;
            const int nout = (tid < 128) ? 2 : 1;
            int plist[2] = { kg, 6 };
            for (int oi = 0; oi < nout; oi++) {
                const int p = plist[oi];
                u64 rv = 0ull, zv = 0ull, iv = 0ull;
                #pragma unroll
                for (int g = 0; g < 4; g++) {
                    const u64* s = red + g*128*R03P + j*R03P;
                    rv = add2(rv, s[p]);
                    zv = add2(zv, s[8+p]);
                    iv = add2(iv, s[16+p]);
                }
                rv = add2(rv, s4[p]);
                zv = add2(zv, s4[8+p]);
                iv = add2(iv, s4[16+p]);
                u64 hv = add2(s4[24+p], s5[p]);
                u64 gv = s5[8+p];

                float r0f,r1f,z0f,z1f,i0f,i1f,n0f,n1f,h0f,h1f;
                unpack2(rv, r0f, r1f);
                unpack2(zv, z0f, z1f);
                unpack2(iv, i0f, i1f);
                unpack2(hv, n0f, n1f);
                unpack2(*reinterpret_cast<u64*>(hrow + 2*p), h0f, h1f);
                float rr0 = sigmoid_fast(r0f + br_);
                float rr1 = sigmoid_fast(r1f + br_);
                float zz0 = sigmoid_fast(z0f + bz_);
                float zz1 = sigmoid_fast(z1f + bz_);
                float nn0 = tanh_fast(i0f + bin_ + rr0 * (n0f + bhn_));
                float nn1 = tanh_fast(i1f + bin_ + rr1 * (n1f + bhn_));
                float hn0 = (1.f - zz0)*nn0 + zz0*h0f;
                float hn1 = (1.f - zz1)*nn1 + zz1*h1f;
                if (t + 1 < T_) {
                    float gp0, gp1;
                    unpack2(gv, gp0, gp1);
                    float gg0 = __expf(-fmaxf(gp0 + bdh_j, 0.f));
                    float gg1 = __expf(-fmaxf(gp1 + bdh_j, 0.f));
                    hn0 *= gg0; hn1 *= gg1;
                }
                *reinterpret_cast<u64*>(hrow + 2*p) = pack2(hn0, hn1);
            }
        }
        __syncthreads();   // S2
    }

    // ---- final: logits = h @ Wc.T + bc ; sigmoid (exact) ----
    if (tid < 128) {
        float part[BR];
        #pragma unroll
        for (int r = 0; r < BR; r++)
            part[r] = hsh[j*UPITCH + r] * wc_j;
        #pragma unroll
        for (int off = 16; off > 0; off >>= 1) {
            #pragma unroll
            for (int r = 0; r < BR; r++)
                part[r] += __shfl_down_sync(0xffffffffu, part[r], off);
        }
        if ((tid & 31) == 0) {
            int w = tid >> 5;
            #pragma unroll
            for (int r = 0; r < BR; r++) s_redf[w*BR + r] = part[r];
        }
    }
    __syncthreads();
    if (tid < BR && (r0 + tid) < B_) {
        float s = s_redf[0*BR + tid] + s_redf[1*BR + tid]
                + s_redf[2*BR + tid] + s_redf[3*BR + tid] + bc[0];
        out[r0 + tid] = sigmoidf_(s);
    }
}

extern "C" void kernel_launch(void* const* d_in, const int* in_sizes, int n_in,
                              void* d_out, int out_size) {
    const float* values   = (const float*)d_in[0];
    const float* masks    = (const float*)d_in[1];
    const float* deltas   = (const float*)d_in[2];
    const float* x_locf   = (const float*)d_in[3];
    const float* emp_mean = (const float*)d_in[4];
    const float* Wdh      = (const float*)d_in[5];
    const float* bdh      = (const float*)d_in[6];
    const float* Wdx      = (const float*)d_in[7];
    const float* bdx      = (const float*)d_in[8];
    const float* w_ih     = (const float*)d_in[9];
    const float* w_hh     = (const float*)d_in[10];
    const float* b_ih     = (const float*)d_in[11];
    const float* b_hh     = (const float*)d_in[12];
    const float* Wc       = (const float*)d_in[13];
    const float* bc       = (const float*)d_in[14];
    float* out = (float*)d_out;

    cudaFuncSetAttribute(grud_kernel,
                         cudaFuncAttributeMaxDynamicSharedMemorySize, SMEM_BYTES);

    prep_kernel<<<576, 256>>>(w_ih, w_hh, Wdh);
    grud_kernel<<<NB, NT, SMEM_BYTES>>>(values, masks, deltas, x_locf, emp_mean,
                                        bdh, Wdx, bdx, b_ih, b_hh, Wc, bc, out);
}